// round 16
// baseline (speedup 1.0000x reference)
#include <cuda_runtime.h>
#include <cuda_bf16.h>
#include <cstdint>

#define GR 8
#define BATCH 32
#define TT 512
#define ROWS 384          // 3 * 128
#define KC 384            // cat-K
#define APAD 392          // smem row stride (bf16)

typedef unsigned long long ull;

// scratch: gx fp32 (201MB), split-bf16 A operand
__device__ float g_gx[(size_t)TT * GR * ROWS * BATCH];
__device__ __nv_bfloat16 g_acat[(size_t)GR * ROWS * KC];         // [g][o][k]

__device__ __forceinline__ ull pk(float lo, float hi) {
    ull r;
    asm("mov.b64 %0, {%1, %2};" : "=l"(r) : "f"(lo), "f"(hi));
    return r;
}
__device__ __forceinline__ float2 up(ull v) {
    float2 r;
    asm("mov.b64 {%0, %1}, %2;" : "=f"(r.x), "=f"(r.y) : "l"(v));
    return r;
}
__device__ __forceinline__ void fma2(ull& d, ull a, ull b) {
    asm("fma.rn.f32x2 %0, %1, %2, %0;" : "+l"(d) : "l"(a), "l"(b));
}
__device__ __forceinline__ float sigm(float x) {
    return __fdividef(1.0f, 1.0f + __expf(-x));
}
__device__ __forceinline__ float tanh_(float x) {
    return 1.0f - __fdividef(2.0f, __expf(2.0f * x) + 1.0f);
}
__device__ __forceinline__ float hadd(ull v) {
    float2 u = up(v);
    return u.x + u.y;
}
__device__ __forceinline__ unsigned sptr(const void* p) {
    return (unsigned)__cvta_generic_to_shared(p);
}
__device__ __forceinline__ ull lds64(uint32_t addr) {
    ull r;
    asm volatile("ld.shared.b64 %0, [%1];" : "=l"(r) : "r"(addr));
    return r;
}
__device__ __forceinline__ void cpa8(unsigned d, const void* s) {
    asm volatile("cp.async.ca.shared.global [%0], [%1], 8;" :: "r"(d), "l"(s));
}
__device__ __forceinline__ void cpa16(unsigned d, const void* s) {
    asm volatile("cp.async.cg.shared.global [%0], [%1], 16;" :: "r"(d), "l"(s));
}
__device__ __forceinline__ void cpcommit() { asm volatile("cp.async.commit_group;" ::: "memory"); }
__device__ __forceinline__ void cpwait0()  { asm volatile("cp.async.wait_group 0;" ::: "memory"); }
__device__ __forceinline__ void cpwait1()  { asm volatile("cp.async.wait_group 1;" ::: "memory"); }

__device__ __forceinline__ void ldm4(uint32_t* r, unsigned addr) {
    asm volatile("ldmatrix.sync.aligned.m8n8.x4.shared.b16 {%0,%1,%2,%3}, [%4];"
                 : "=r"(r[0]), "=r"(r[1]), "=r"(r[2]), "=r"(r[3]) : "r"(addr));
}
__device__ __forceinline__ void mma16816(float* d, const uint32_t* a, const uint32_t* b) {
    asm volatile(
        "mma.sync.aligned.m16n8k16.row.col.f32.bf16.bf16.f32 "
        "{%0,%1,%2,%3}, {%4,%5,%6,%7}, {%8,%9}, {%0,%1,%2,%3};"
        : "+f"(d[0]), "+f"(d[1]), "+f"(d[2]), "+f"(d[3])
        : "r"(a[0]), "r"(a[1]), "r"(a[2]), "r"(a[3]), "r"(b[0]), "r"(b[1]));
}
__device__ __forceinline__ uint32_t pkbf(float v0, float v1) {
    __nv_bfloat16 b0 = __float2bfloat16(v0);
    __nv_bfloat16 b1 = __float2bfloat16(v1);
    return (uint32_t)__bfloat16_as_ushort(b0) | ((uint32_t)__bfloat16_as_ushort(b1) << 16);
}

// ============================================================================
// prep_w: A_cat[g][o] = [bf16(W) | bf16(W) | Wlo] over k
// ============================================================================
__global__ void prep_w(const float* __restrict__ W_ih)
{
    int idx = blockIdx.x * 256 + threadIdx.x;
    if (idx >= GR * ROWS * 128) return;
    float v = W_ih[idx];
    int k = idx & 127;
    int go = idx >> 7;
    __nv_bfloat16 hi = __float2bfloat16(v);
    __nv_bfloat16 lo = __float2bfloat16(v - __bfloat162float(hi));
    __nv_bfloat16* dst = g_acat + (size_t)go * KC;
    dst[k] = hi; dst[128 + k] = hi; dst[256 + k] = lo;
}

// ============================================================================
// gx_mma (R12, best): CTA (g, mt, tb): D[128 x 64] = A[128 x 384]*B[64 x 384]^T
// per pass (2 timesteps), 16 passes. A staged once via cp.async from g_acat;
// B converted in-kernel from fp32 x (LDG early, convert+STS after mma loop).
// 256 threads, warp grid 4(m) x 2(n); warp-n == timestep-in-pair.
// ============================================================================
#define A_SM_BYTES (128 * APAD * 2)      // 100,352
#define B_SM_BYTES (64 * APAD * 2)       // 50,176

__global__ void __launch_bounds__(256, 1)
gx_mma(const float* __restrict__ x, const float* __restrict__ b_ih)
{
    extern __shared__ __align__(1024) char smx[];      // A | B0 | B1
    const int bx  = blockIdx.x;                        // 8g * 48
    const int g   = bx & 7;
    const int r   = bx >> 3;
    const int mt  = r % 3;
    const int tb  = r / 3;
    const int tid = threadIdx.x;
    const int wid = tid >> 5;
    const int lane = tid & 31;
    const int wm  = wid >> 1;           // 0..3 (m)
    const int wn  = wid & 1;            // 0..1 (n == tloc)

    const uint32_t Abase = sptr(smx);
    char* Bsm = smx + A_SM_BYTES;

    // ---- stage A once (cp.async) ----
    {
        const __nv_bfloat16* src = g_acat + ((size_t)g * ROWS + mt * 128) * KC;
        for (int c = tid; c < 128 * 48; c += 256) {
            int row = c / 48, kc = c % 48;
            cpa16(Abase + row * (APAD * 2) + kc * 16, src + (size_t)row * KC + kc * 8);
        }
    }
    cpcommit();

    // staging geometry: thread -> (batch brow, 16-float k-chunk), BOTH tlocs
    const int brow = tid >> 3;          // 0..31
    const int k0   = (tid & 7) * 16;    // 0..112
    const float* xrow = x + ((size_t)brow * TT + tb * 32) * 1024 + g * 128 + k0;

    auto cvt_store = [&](const float* v, char* dst) {
        uint32_t hiw[8], low[8];
#pragma unroll
        for (int i = 0; i < 8; i++) {
            float v0 = v[2 * i], v1 = v[2 * i + 1];
            hiw[i] = pkbf(v0, v1);
            float h0 = __bfloat162float(__float2bfloat16(v0));
            float h1 = __bfloat162float(__float2bfloat16(v1));
            low[i] = pkbf(v0 - h0, v1 - h1);
        }
        *(uint4*)(dst)            = make_uint4(hiw[0], hiw[1], hiw[2], hiw[3]);
        *(uint4*)(dst + 16)       = make_uint4(hiw[4], hiw[5], hiw[6], hiw[7]);
        *(uint4*)(dst + 256)      = make_uint4(low[0], low[1], low[2], low[3]);
        *(uint4*)(dst + 256 + 16) = make_uint4(low[4], low[5], low[6], low[7]);
        *(uint4*)(dst + 512)      = make_uint4(hiw[0], hiw[1], hiw[2], hiw[3]);
        *(uint4*)(dst + 512 + 16) = make_uint4(hiw[4], hiw[5], hiw[6], hiw[7]);
    };
    const int dst_off0 = brow * (APAD * 2) + k0 * 2;          // row tloc=0
    const int dst_off1 = (32 + brow) * (APAD * 2) + k0 * 2;   // row tloc=1

    // ---- prologue: load + convert pass 0 into B0 ----
    {
        float vs[32];
#pragma unroll
        for (int i = 0; i < 4; i++) {
            *(float4*)(vs + 4 * i)      = *(const float4*)(xrow + 4 * i);
            *(float4*)(vs + 16 + 4 * i) = *(const float4*)(xrow + 1024 + 4 * i);
        }
        cvt_store(vs,      Bsm + dst_off0);
        cvt_store(vs + 16, Bsm + dst_off1);
    }
    cpwait0();          // A complete
    __syncthreads();

    const uint32_t Bbase = sptr(Bsm);
    const uint32_t aoffs = (uint32_t)(wm * 32 + (lane & 15)) * (APAD * 2) + ((lane >> 4) << 3) * 2;
    const uint32_t boffs = (uint32_t)(wn * 32 + ((lane >> 4) << 3) + (lane & 7)) * (APAD * 2)
                         + (((lane >> 3) & 1) << 3) * 2;

    const int gid = lane >> 2;
    const int tg  = lane & 3;

    const int ob = mt * 128 + wm * 32 + gid;
    float bias[2][2];
    bias[0][0] = b_ih[g * ROWS + ob];
    bias[0][1] = b_ih[g * ROWS + ob + 8];
    bias[1][0] = b_ih[g * ROWS + ob + 16];
    bias[1][1] = b_ih[g * ROWS + ob + 24];

    float* gout = g_gx + ((size_t)(tb * 32 + wn) * GR + g) * ROWS * BATCH
                + (size_t)(mt * 128 + wm * 32 + gid) * BATCH + tg * 2;
    const size_t gstep = (size_t)GR * ROWS * BATCH;

    for (int p = 0; p < 16; p++) {
        float vs[32];
        if (p < 15) {
            const float* xp = xrow + (size_t)((p + 1) * 2) * 1024;
#pragma unroll
            for (int i = 0; i < 4; i++) {
                *(float4*)(vs + 4 * i)      = *(const float4*)(xp + 4 * i);
                *(float4*)(vs + 16 + 4 * i) = *(const float4*)(xp + 1024 + 4 * i);
            }
        }

        const uint32_t Bt = Bbase + (p & 1) * B_SM_BYTES;

        float d[2][4][4];
#pragma unroll
        for (int i = 0; i < 2; i++)
#pragma unroll
            for (int nt = 0; nt < 4; nt++)
#pragma unroll
                for (int e = 0; e < 4; e++) d[i][nt][e] = 0.f;

#pragma unroll
        for (int ks = 0; ks < 24; ks++) {
            const uint32_t kk = ks * 32;
            uint32_t a0[4], a1[4], bA[4], bB[4];
            ldm4(a0, Abase + aoffs + kk);
            ldm4(a1, Abase + aoffs + 16 * (APAD * 2) + kk);
            ldm4(bA, Bt + boffs + kk);
            ldm4(bB, Bt + boffs + 16 * (APAD * 2) + kk);
            mma16816(d[0][0], a0, bA);
            mma16816(d[0][1], a0, bA + 2);
            mma16816(d[0][2], a0, bB);
            mma16816(d[0][3], a0, bB + 2);
            mma16816(d[1][0], a1, bA);
            mma16816(d[1][1], a1, bA + 2);
            mma16816(d[1][2], a1, bB);
            mma16816(d[1][3], a1, bB + 2);
        }

        if (p < 15) {
            char* bd = Bsm + ((p + 1) & 1) * B_SM_BYTES;
            cvt_store(vs,      bd + dst_off0);
            cvt_store(vs + 16, bd + dst_off1);
        }

        float* op = gout + (size_t)(p * 2) * gstep;
#pragma unroll
        for (int i = 0; i < 2; i++) {
#pragma unroll
            for (int nt = 0; nt < 4; nt++) {
                float2 v0 = make_float2(d[i][nt][0] + bias[i][0], d[i][nt][1] + bias[i][0]);
                float2 v1 = make_float2(d[i][nt][2] + bias[i][1], d[i][nt][3] + bias[i][1]);
                *(float2*)(op + (size_t)(i * 16) * BATCH + nt * 8)     = v0;
                *(float2*)(op + (size_t)(i * 16 + 8) * BATCH + nt * 8) = v1;
            }
        }
        __syncthreads();
    }
}

// ============================================================================
// Phase 2: recurrence — R4 structure, but K-loop h-loads forced to LDS.64
// (ld.shared.b64): each warp has only 4 distinct h-addresses (8-way lane
// broadcast); at 8B width the crossbar can dedup (N=1 rule) where LDS.128
// pays full wavefronts. Identical registers/semantics otherwise.
// ============================================================================
__global__ void __launch_bounds__(512, 1)
gru_kernel(const float* __restrict__ state,
           const float* __restrict__ W_hh,
           const float* __restrict__ b_hh,
           float* __restrict__ out)
{
    __shared__ __align__(16) float Hb0[2][144];
    __shared__ __align__(16) float Hb1[2][144];
    __shared__ __align__(16) float Gs[3][ROWS * 2];

    const int g   = blockIdx.x >> 4;
    const int bp  = blockIdx.x & 15;
    const int tid = threadIdx.x;
    const int j   = tid >> 2;
    const int q   = tid & 3;
    const int b0  = bp * 2;

    ull wr[16], wz[16], wn[16];
    {
        const float* base = W_hh + (size_t)g * ROWS * 128 + q * 32;
        const float* pr = base + (size_t)(j)       * 128;
        const float* pz = base + (size_t)(128 + j) * 128;
        const float* pn = base + (size_t)(256 + j) * 128;
#pragma unroll
        for (int i = 0; i < 8; i++) {
            ulonglong2 a = *(const ulonglong2*)(pr + i * 4);
            wr[2 * i] = a.x; wr[2 * i + 1] = a.y;
            ulonglong2 b = *(const ulonglong2*)(pz + i * 4);
            wz[2 * i] = b.x; wz[2 * i + 1] = b.y;
            ulonglong2 c = *(const ulonglong2*)(pn + i * 4);
            wn[2 * i] = c.x; wn[2 * i + 1] = c.y;
        }
    }

    const float bhr = b_hh[g * ROWS + j];
    const float bhz = b_hh[g * ROWS + 128 + j];
    const float bhn = b_hh[g * ROWS + 256 + j];

    const int jsw = (j >> 5) * 36 + (j & 31);

    if (q == 0) Hb0[0][jsw] = state[((size_t)g * 32 + b0) * 128 + j];
    if (q == 1) Hb1[0][jsw] = state[((size_t)g * 32 + b0 + 1) * 128 + j];

    const size_t stride_t = (size_t)GR * ROWS * BATCH;
    const float* gx0 = g_gx + (size_t)g * ROWS * BATCH + b0;

    const float* gxt = gx0 + (size_t)tid * BATCH;
    if (tid < ROWS) cpa8(sptr(&Gs[0][tid * 2]), gxt);
    cpcommit();
    if (tid < ROWS) cpa8(sptr(&Gs[1][tid * 2]), gxt + stride_t);
    cpcommit();
    gxt += 2 * stride_t;
    cpwait1();
    __syncthreads();

    const int myb = q >> 1;
    float* outp = out + ((size_t)(b0 + myb) * TT) * 1024 + g * 128 + j;

    const int qoff = q * 36;
    // shared-space base addresses for the two ping-pong h buffers
    const uint32_t h0a[2] = { sptr(&Hb0[0][qoff]), sptr(&Hb0[1][qoff]) };
    const uint32_t h1a[2] = { sptr(&Hb1[0][qoff]), sptr(&Hb1[1][qoff]) };

    int p = 0, cb = 0;

    for (int t = 0; t < TT; t++) {
        {
            int nb = cb + 2; if (nb >= 3) nb -= 3;
            if (t + 2 < TT && tid < ROWS)
                cpa8(sptr(&Gs[nb][tid * 2]), gxt);
            cpcommit();
            gxt += stride_t;
        }

        const uint32_t a0 = h0a[p];
        const uint32_t a1 = h1a[p];

        ull ar0 = 0, az0 = 0, an0 = 0;
        ull ar1 = 0, az1 = 0, an1 = 0;

#pragma unroll
        for (int i = 0; i < 8; i++) {
            ull h0x = lds64(a0 + i * 16);
            ull h0y = lds64(a0 + i * 16 + 8);
            ull h1x = lds64(a1 + i * 16);
            ull h1y = lds64(a1 + i * 16 + 8);
            fma2(ar0, wr[2 * i],     h0x);
            fma2(az0, wz[2 * i],     h0x);
            fma2(an0, wn[2 * i],     h0x);
            fma2(ar1, wr[2 * i],     h1x);
            fma2(az1, wz[2 * i],     h1x);
            fma2(an1, wn[2 * i],     h1x);
            fma2(ar0, wr[2 * i + 1], h0y);
            fma2(az0, wz[2 * i + 1], h0y);
            fma2(an0, wn[2 * i + 1], h0y);
            fma2(ar1, wr[2 * i + 1], h1y);
            fma2(az1, wz[2 * i + 1], h1y);
            fma2(an1, wn[2 * i + 1], h1y);
        }

        float sr0 = hadd(ar0), sz0 = hadd(az0), sn0 = hadd(an0);
        float sr1 = hadd(ar1), sz1 = hadd(az1), sn1 = hadd(an1);

        const bool hi = (q & 2) != 0;
        float vr = hi ? sr0 : sr1;
        float vz = hi ? sz0 : sz1;
        float vn = hi ? sn0 : sn1;
        float kr = hi ? sr1 : sr0;
        float kz = hi ? sz1 : sz0;
        float kn = hi ? sn1 : sn0;
        kr += __shfl_xor_sync(0xffffffffu, vr, 2);
        kz += __shfl_xor_sync(0xffffffffu, vz, 2);
        kn += __shfl_xor_sync(0xffffffffu, vn, 2);
        kr += __shfl_xor_sync(0xffffffffu, kr, 1);
        kz += __shfl_xor_sync(0xffffffffu, kz, 1);
        kn += __shfl_xor_sync(0xffffffffu, kn, 1);

        const float* Gc = Gs[cb];
        float gr_ = Gc[(j)       * 2 + myb];
        float gz_ = Gc[(128 + j) * 2 + myb];
        float gn_ = Gc[(256 + j) * 2 + myb];
        float hold = (hi ? Hb1[p] : Hb0[p])[jsw];

        float rr = sigm(gr_ + kr + bhr);
        float zz = sigm(gz_ + kz + bhz);
        float nn = tanh_(gn_ + rr * (kn + bhn));
        float hn = nn + zz * (hold - nn);

        const int np = p ^ 1;
        if (q == 0) {
            Hb0[np][jsw] = hn;
        } else if (q == 2) {
            Hb1[np][jsw] = hn;
        } else {
            *outp = hn;
        }
        outp += 1024;

        cpwait1();
        __syncthreads();
        p = np;
        cb = cb + 1; if (cb >= 3) cb -= 3;
    }

    float* hop = out + (size_t)BATCH * TT * 1024;
    if (q == 0) hop[((size_t)g * 32 + b0) * 128 + j]     = Hb0[p][jsw];
    if (q == 2) hop[((size_t)g * 32 + b0 + 1) * 128 + j] = Hb1[p][jsw];
}

extern "C" void kernel_launch(void* const* d_in, const int* in_sizes, int n_in,
                              void* d_out, int out_size)
{
    const float* x     = (const float*)d_in[0];
    const float* state = (const float*)d_in[1];
    const float* W_ih  = (const float*)d_in[2];
    const float* W_hh  = (const float*)d_in[3];
    const float* b_ih  = (const float*)d_in[4];
    const float* b_hh  = (const float*)d_in[5];
    float* out = (float*)d_out;

    const int smem_mma = A_SM_BYTES + 2 * B_SM_BYTES;   // 200,704
    cudaFuncSetAttribute(gx_mma, cudaFuncAttributeMaxDynamicSharedMemorySize, smem_mma);

    prep_w<<<1536, 256>>>(W_ih);
    gx_mma<<<384, 256, smem_mma>>>(x, b_ih);
    gru_kernel<<<128, 512>>>(state, W_hh, b_hh, out);
}

// round 17
// speedup vs baseline: 1.0545x; 1.0545x over previous
#include <cuda_runtime.h>
#include <cuda_bf16.h>
#include <cstdint>

#define GR 8
#define BATCH 32
#define TT 512
#define ROWS 384          // 3 * 128
#define KC 384            // cat-K
#define APAD 392          // smem row stride (bf16)

typedef unsigned long long ull;

// scratch: gx fp32 (201MB), split-bf16 A operand
__device__ float g_gx[(size_t)TT * GR * ROWS * BATCH];
__device__ __nv_bfloat16 g_acat[(size_t)GR * ROWS * KC];         // [g][o][k]

__device__ __forceinline__ ull pk(float lo, float hi) {
    ull r;
    asm("mov.b64 %0, {%1, %2};" : "=l"(r) : "f"(lo), "f"(hi));
    return r;
}
__device__ __forceinline__ float2 up(ull v) {
    float2 r;
    asm("mov.b64 {%0, %1}, %2;" : "=f"(r.x), "=f"(r.y) : "l"(v));
    return r;
}
__device__ __forceinline__ void fma2(ull& d, ull a, ull b) {
    asm("fma.rn.f32x2 %0, %1, %2, %0;" : "+l"(d) : "l"(a), "l"(b));
}
__device__ __forceinline__ float sigm(float x) {
    return __fdividef(1.0f, 1.0f + __expf(-x));
}
__device__ __forceinline__ float tanh_(float x) {
    return 1.0f - __fdividef(2.0f, __expf(2.0f * x) + 1.0f);
}
__device__ __forceinline__ float hadd(ull v) {
    float2 u = up(v);
    return u.x + u.y;
}
__device__ __forceinline__ unsigned sptr(const void* p) {
    return (unsigned)__cvta_generic_to_shared(p);
}
__device__ __forceinline__ void cpa8(unsigned d, const void* s) {
    asm volatile("cp.async.ca.shared.global [%0], [%1], 8;" :: "r"(d), "l"(s));
}
__device__ __forceinline__ void cpa16(unsigned d, const void* s) {
    asm volatile("cp.async.cg.shared.global [%0], [%1], 16;" :: "r"(d), "l"(s));
}
__device__ __forceinline__ void cpcommit() { asm volatile("cp.async.commit_group;" ::: "memory"); }
__device__ __forceinline__ void cpwait0()  { asm volatile("cp.async.wait_group 0;" ::: "memory"); }
__device__ __forceinline__ void cpwait1()  { asm volatile("cp.async.wait_group 1;" ::: "memory"); }

__device__ __forceinline__ void stg_cs_f32(float* p, float v) {
    asm volatile("st.global.cs.f32 [%0], %1;" :: "l"(p), "f"(v));
}
__device__ __forceinline__ void stg_cs_v2(float* p, float a, float b) {
    asm volatile("st.global.cs.v2.f32 [%0], {%1, %2};" :: "l"(p), "f"(a), "f"(b));
}

__device__ __forceinline__ void ldm4(uint32_t* r, unsigned addr) {
    asm volatile("ldmatrix.sync.aligned.m8n8.x4.shared.b16 {%0,%1,%2,%3}, [%4];"
                 : "=r"(r[0]), "=r"(r[1]), "=r"(r[2]), "=r"(r[3]) : "r"(addr));
}
__device__ __forceinline__ void mma16816(float* d, const uint32_t* a, const uint32_t* b) {
    asm volatile(
        "mma.sync.aligned.m16n8k16.row.col.f32.bf16.bf16.f32 "
        "{%0,%1,%2,%3}, {%4,%5,%6,%7}, {%8,%9}, {%0,%1,%2,%3};"
        : "+f"(d[0]), "+f"(d[1]), "+f"(d[2]), "+f"(d[3])
        : "r"(a[0]), "r"(a[1]), "r"(a[2]), "r"(a[3]), "r"(b[0]), "r"(b[1]));
}
__device__ __forceinline__ uint32_t pkbf(float v0, float v1) {
    __nv_bfloat16 b0 = __float2bfloat16(v0);
    __nv_bfloat16 b1 = __float2bfloat16(v1);
    return (uint32_t)__bfloat16_as_ushort(b0) | ((uint32_t)__bfloat16_as_ushort(b1) << 16);
}

// ============================================================================
// prep_w: A_cat[g][o] = [bf16(W) | bf16(W) | Wlo] over k
// ============================================================================
__global__ void prep_w(const float* __restrict__ W_ih)
{
    int idx = blockIdx.x * 256 + threadIdx.x;
    if (idx >= GR * ROWS * 128) return;
    float v = W_ih[idx];
    int k = idx & 127;
    int go = idx >> 7;
    __nv_bfloat16 hi = __float2bfloat16(v);
    __nv_bfloat16 lo = __float2bfloat16(v - __bfloat162float(hi));
    __nv_bfloat16* dst = g_acat + (size_t)go * KC;
    dst[k] = hi; dst[128 + k] = hi; dst[256 + k] = lo;
}

// ============================================================================
// gx_mma (R12/R13, best): CTA (g, mt, tb): D[128x64] = A[128x384]*B[64x384]^T
// per pass (2 timesteps), 16 passes. A staged once via cp.async; B converted
// in-kernel from fp32 x. 256 threads, warp grid 4(m) x 2(n); warp-n == tloc.
// Epilogue stores use st.global.cs (g_gx is write-once streaming).
// ============================================================================
#define A_SM_BYTES (128 * APAD * 2)      // 100,352
#define B_SM_BYTES (64 * APAD * 2)       // 50,176

__global__ void __launch_bounds__(256, 1)
gx_mma(const float* __restrict__ x, const float* __restrict__ b_ih)
{
    extern __shared__ __align__(1024) char smx[];      // A | B0 | B1
    const int bx  = blockIdx.x;                        // 8g * 48
    const int g   = bx & 7;
    const int r   = bx >> 3;
    const int mt  = r % 3;
    const int tb  = r / 3;
    const int tid = threadIdx.x;
    const int wid = tid >> 5;
    const int lane = tid & 31;
    const int wm  = wid >> 1;           // 0..3 (m)
    const int wn  = wid & 1;            // 0..1 (n == tloc)

    const uint32_t Abase = sptr(smx);
    char* Bsm = smx + A_SM_BYTES;

    // ---- stage A once (cp.async) ----
    {
        const __nv_bfloat16* src = g_acat + ((size_t)g * ROWS + mt * 128) * KC;
        for (int c = tid; c < 128 * 48; c += 256) {
            int row = c / 48, kc = c % 48;
            cpa16(Abase + row * (APAD * 2) + kc * 16, src + (size_t)row * KC + kc * 8);
        }
    }
    cpcommit();

    // staging geometry: thread -> (batch brow, 16-float k-chunk), BOTH tlocs
    const int brow = tid >> 3;          // 0..31
    const int k0   = (tid & 7) * 16;    // 0..112
    const float* xrow = x + ((size_t)brow * TT + tb * 32) * 1024 + g * 128 + k0;

    auto cvt_store = [&](const float* v, char* dst) {
        uint32_t hiw[8], low[8];
#pragma unroll
        for (int i = 0; i < 8; i++) {
            float v0 = v[2 * i], v1 = v[2 * i + 1];
            hiw[i] = pkbf(v0, v1);
            float h0 = __bfloat162float(__float2bfloat16(v0));
            float h1 = __bfloat162float(__float2bfloat16(v1));
            low[i] = pkbf(v0 - h0, v1 - h1);
        }
        *(uint4*)(dst)            = make_uint4(hiw[0], hiw[1], hiw[2], hiw[3]);
        *(uint4*)(dst + 16)       = make_uint4(hiw[4], hiw[5], hiw[6], hiw[7]);
        *(uint4*)(dst + 256)      = make_uint4(low[0], low[1], low[2], low[3]);
        *(uint4*)(dst + 256 + 16) = make_uint4(low[4], low[5], low[6], low[7]);
        *(uint4*)(dst + 512)      = make_uint4(hiw[0], hiw[1], hiw[2], hiw[3]);
        *(uint4*)(dst + 512 + 16) = make_uint4(hiw[4], hiw[5], hiw[6], hiw[7]);
    };
    const int dst_off0 = brow * (APAD * 2) + k0 * 2;          // row tloc=0
    const int dst_off1 = (32 + brow) * (APAD * 2) + k0 * 2;   // row tloc=1

    // ---- prologue: load + convert pass 0 into B0 ----
    {
        float vs[32];
#pragma unroll
        for (int i = 0; i < 4; i++) {
            *(float4*)(vs + 4 * i)      = *(const float4*)(xrow + 4 * i);
            *(float4*)(vs + 16 + 4 * i) = *(const float4*)(xrow + 1024 + 4 * i);
        }
        cvt_store(vs,      Bsm + dst_off0);
        cvt_store(vs + 16, Bsm + dst_off1);
    }
    cpwait0();          // A complete
    __syncthreads();

    const uint32_t Bbase = sptr(Bsm);
    const uint32_t aoffs = (uint32_t)(wm * 32 + (lane & 15)) * (APAD * 2) + ((lane >> 4) << 3) * 2;
    const uint32_t boffs = (uint32_t)(wn * 32 + ((lane >> 4) << 3) + (lane & 7)) * (APAD * 2)
                         + (((lane >> 3) & 1) << 3) * 2;

    const int gid = lane >> 2;
    const int tg  = lane & 3;

    const int ob = mt * 128 + wm * 32 + gid;
    float bias[2][2];
    bias[0][0] = b_ih[g * ROWS + ob];
    bias[0][1] = b_ih[g * ROWS + ob + 8];
    bias[1][0] = b_ih[g * ROWS + ob + 16];
    bias[1][1] = b_ih[g * ROWS + ob + 24];

    float* gout = g_gx + ((size_t)(tb * 32 + wn) * GR + g) * ROWS * BATCH
                + (size_t)(mt * 128 + wm * 32 + gid) * BATCH + tg * 2;
    const size_t gstep = (size_t)GR * ROWS * BATCH;

    for (int p = 0; p < 16; p++) {
        float vs[32];
        if (p < 15) {
            const float* xp = xrow + (size_t)((p + 1) * 2) * 1024;
#pragma unroll
            for (int i = 0; i < 4; i++) {
                *(float4*)(vs + 4 * i)      = *(const float4*)(xp + 4 * i);
                *(float4*)(vs + 16 + 4 * i) = *(const float4*)(xp + 1024 + 4 * i);
            }
        }

        const uint32_t Bt = Bbase + (p & 1) * B_SM_BYTES;

        float d[2][4][4];
#pragma unroll
        for (int i = 0; i < 2; i++)
#pragma unroll
            for (int nt = 0; nt < 4; nt++)
#pragma unroll
                for (int e = 0; e < 4; e++) d[i][nt][e] = 0.f;

#pragma unroll
        for (int ks = 0; ks < 24; ks++) {
            const uint32_t kk = ks * 32;
            uint32_t a0[4], a1[4], bA[4], bB[4];
            ldm4(a0, Abase + aoffs + kk);
            ldm4(a1, Abase + aoffs + 16 * (APAD * 2) + kk);
            ldm4(bA, Bt + boffs + kk);
            ldm4(bB, Bt + boffs + 16 * (APAD * 2) + kk);
            mma16816(d[0][0], a0, bA);
            mma16816(d[0][1], a0, bA + 2);
            mma16816(d[0][2], a0, bB);
            mma16816(d[0][3], a0, bB + 2);
            mma16816(d[1][0], a1, bA);
            mma16816(d[1][1], a1, bA + 2);
            mma16816(d[1][2], a1, bB);
            mma16816(d[1][3], a1, bB + 2);
        }

        if (p < 15) {
            char* bd = Bsm + ((p + 1) & 1) * B_SM_BYTES;
            cvt_store(vs,      bd + dst_off0);
            cvt_store(vs + 16, bd + dst_off1);
        }

        float* op = gout + (size_t)(p * 2) * gstep;
#pragma unroll
        for (int i = 0; i < 2; i++) {
#pragma unroll
            for (int nt = 0; nt < 4; nt++) {
                stg_cs_v2(op + (size_t)(i * 16) * BATCH + nt * 8,
                          d[i][nt][0] + bias[i][0], d[i][nt][1] + bias[i][0]);
                stg_cs_v2(op + (size_t)(i * 16 + 8) * BATCH + nt * 8,
                          d[i][nt][2] + bias[i][1], d[i][nt][3] + bias[i][1]);
            }
        }
        __syncthreads();
    }
}

// ============================================================================
// Phase 2: recurrence — R4 VERBATIM (best: ~600us); out stores use .cs.
// ============================================================================
__global__ void __launch_bounds__(512, 1)
gru_kernel(const float* __restrict__ state,
           const float* __restrict__ W_hh,
           const float* __restrict__ b_hh,
           float* __restrict__ out)
{
    __shared__ __align__(16) float Hb0[2][144];
    __shared__ __align__(16) float Hb1[2][144];
    __shared__ __align__(16) float Gs[3][ROWS * 2];

    const int g   = blockIdx.x >> 4;
    const int bp  = blockIdx.x & 15;
    const int tid = threadIdx.x;
    const int j   = tid >> 2;
    const int q   = tid & 3;
    const int b0  = bp * 2;

    ull wr[16], wz[16], wn[16];
    {
        const float* base = W_hh + (size_t)g * ROWS * 128 + q * 32;
        const float* pr = base + (size_t)(j)       * 128;
        const float* pz = base + (size_t)(128 + j) * 128;
        const float* pn = base + (size_t)(256 + j) * 128;
#pragma unroll
        for (int i = 0; i < 8; i++) {
            ulonglong2 a = *(const ulonglong2*)(pr + i * 4);
            wr[2 * i] = a.x; wr[2 * i + 1] = a.y;
            ulonglong2 b = *(const ulonglong2*)(pz + i * 4);
            wz[2 * i] = b.x; wz[2 * i + 1] = b.y;
            ulonglong2 c = *(const ulonglong2*)(pn + i * 4);
            wn[2 * i] = c.x; wn[2 * i + 1] = c.y;
        }
    }

    const float bhr = b_hh[g * ROWS + j];
    const float bhz = b_hh[g * ROWS + 128 + j];
    const float bhn = b_hh[g * ROWS + 256 + j];

    const int jsw = (j >> 5) * 36 + (j & 31);

    if (q == 0) Hb0[0][jsw] = state[((size_t)g * 32 + b0) * 128 + j];
    if (q == 1) Hb1[0][jsw] = state[((size_t)g * 32 + b0 + 1) * 128 + j];

    const size_t stride_t = (size_t)GR * ROWS * BATCH;
    const float* gx0 = g_gx + (size_t)g * ROWS * BATCH + b0;

    const float* gxt = gx0 + (size_t)tid * BATCH;
    if (tid < ROWS) cpa8(sptr(&Gs[0][tid * 2]), gxt);
    cpcommit();
    if (tid < ROWS) cpa8(sptr(&Gs[1][tid * 2]), gxt + stride_t);
    cpcommit();
    gxt += 2 * stride_t;
    cpwait1();
    __syncthreads();

    const int myb = q >> 1;
    float* outp = out + ((size_t)(b0 + myb) * TT) * 1024 + g * 128 + j;

    const int qoff = q * 36;
    int p = 0, cb = 0;

    for (int t = 0; t < TT; t++) {
        {
            int nb = cb + 2; if (nb >= 3) nb -= 3;
            if (t + 2 < TT && tid < ROWS)
                cpa8(sptr(&Gs[nb][tid * 2]), gxt);
            cpcommit();
            gxt += stride_t;
        }

        const float* H0 = Hb0[p];
        const float* H1 = Hb1[p];

        ull ar0 = 0, az0 = 0, an0 = 0;
        ull ar1 = 0, az1 = 0, an1 = 0;

#pragma unroll
        for (int i = 0; i < 8; i++) {
            ulonglong2 h0 = *(const ulonglong2*)(H0 + qoff + i * 4);
            ulonglong2 h1 = *(const ulonglong2*)(H1 + qoff + i * 4);
            fma2(ar0, wr[2 * i],     h0.x);
            fma2(az0, wz[2 * i],     h0.x);
            fma2(an0, wn[2 * i],     h0.x);
            fma2(ar1, wr[2 * i],     h1.x);
            fma2(az1, wz[2 * i],     h1.x);
            fma2(an1, wn[2 * i],     h1.x);
            fma2(ar0, wr[2 * i + 1], h0.y);
            fma2(az0, wz[2 * i + 1], h0.y);
            fma2(an0, wn[2 * i + 1], h0.y);
            fma2(ar1, wr[2 * i + 1], h1.y);
            fma2(az1, wz[2 * i + 1], h1.y);
            fma2(an1, wn[2 * i + 1], h1.y);
        }

        float sr0 = hadd(ar0), sz0 = hadd(az0), sn0 = hadd(an0);
        float sr1 = hadd(ar1), sz1 = hadd(az1), sn1 = hadd(an1);

        const bool hi = (q & 2) != 0;
        float vr = hi ? sr0 : sr1;
        float vz = hi ? sz0 : sz1;
        float vn = hi ? sn0 : sn1;
        float kr = hi ? sr1 : sr0;
        float kz = hi ? sz1 : sz0;
        float kn = hi ? sn1 : sn0;
        kr += __shfl_xor_sync(0xffffffffu, vr, 2);
        kz += __shfl_xor_sync(0xffffffffu, vz, 2);
        kn += __shfl_xor_sync(0xffffffffu, vn, 2);
        kr += __shfl_xor_sync(0xffffffffu, kr, 1);
        kz += __shfl_xor_sync(0xffffffffu, kz, 1);
        kn += __shfl_xor_sync(0xffffffffu, kn, 1);

        const float* Gc = Gs[cb];
        float gr_ = Gc[(j)       * 2 + myb];
        float gz_ = Gc[(128 + j) * 2 + myb];
        float gn_ = Gc[(256 + j) * 2 + myb];
        float hold = (hi ? H1 : H0)[jsw];

        float rr = sigm(gr_ + kr + bhr);
        float zz = sigm(gz_ + kz + bhz);
        float nn = tanh_(gn_ + rr * (kn + bhn));
        float hn = nn + zz * (hold - nn);

        const int np = p ^ 1;
        if (q == 0) {
            Hb0[np][jsw] = hn;
        } else if (q == 2) {
            Hb1[np][jsw] = hn;
        } else {
            stg_cs_f32(outp, hn);
        }
        outp += 1024;

        cpwait1();
        __syncthreads();
        p = np;
        cb = cb + 1; if (cb >= 3) cb -= 3;
    }

    float* hop = out + (size_t)BATCH * TT * 1024;
    if (q == 0) hop[((size_t)g * 32 + b0) * 128 + j]     = Hb0[p][jsw];
    if (q == 2) hop[((size_t)g * 32 + b0 + 1) * 128 + j] = Hb1[p][jsw];
}

extern "C" void kernel_launch(void* const* d_in, const int* in_sizes, int n_in,
                              void* d_out, int out_size)
{
    const float* x     = (const float*)d_in[0];
    const float* state = (const float*)d_in[1];
    const float* W_ih  = (const float*)d_in[2];
    const float* W_hh  = (const float*)d_in[3];
    const float* b_ih  = (const float*)d_in[4];
    const float* b_hh  = (const float*)d_in[5];
    float* out = (float*)d_out;

    const int smem_mma = A_SM_BYTES + 2 * B_SM_BYTES;   // 200,704
    cudaFuncSetAttribute(gx_mma, cudaFuncAttributeMaxDynamicSharedMemorySize, smem_mma);

    prep_w<<<1536, 256>>>(W_ih);
    gx_mma<<<384, 256, smem_mma>>>(x, b_ih);
    gru_kernel<<<128, 512>>>(state, W_hh, b_hh, out);
}